// round 12
// baseline (speedup 1.0000x reference)
#include <cuda_runtime.h>
#include <cuda.h>
#include <cstdint>

// ---------------- constants ----------------
#define TT    9
#define BB    8
#define CC    256
#define HWHW  3136
#define PIX   8
#define NTHREADS 512
#define TILES_PER_B 392          // 3136/8
#define GRID  296                // 2 persistent CTAs per SM

#define H0_T  4                  // t = 0..3
#define H1_T  5                  // t = 4..8
#define H0_BYTES (H0_T*CC*PIX*4) // 32768
#define H1_BYTES (H1_T*CC*PIX*4) // 40960
#define A_FLOATS (H0_T*CC*PIX)   // 8192
#define TILE_FLOATS (TT*CC*PIX)  // 18432 floats = 73728 B

// SMEM layout (float offsets)
#define OFF_TILE 0                           // [TT*CC*PIX]
#define OFF_PART (TILE_FLOATS)               // 18432  [16 warps][80]
#define OFF_SCOR (OFF_PART + 16*80)          // 19712  [80]
#define OFF_MBAR (OFF_SCOR + 80)             // 19792  (2 x u64; byte 79168, 8B aligned)
#define SMEM_FLOATS (OFF_MBAR + 4)
#define SMEM_BYTES  (SMEM_FLOATS * 4)        // 79184 B  (x2 CTAs = 158368 < 227KB)

// ---------------- PTX helpers ----------------
#define MBAR_INIT(addr, cnt) \
    asm volatile("mbarrier.init.shared.b64 [%0], %1;" :: "r"(addr), "r"(cnt) : "memory")
#define MBAR_EXPECT_TX(addr, bytes) \
    asm volatile("mbarrier.arrive.expect_tx.shared.b64 _, [%0], %1;" :: "r"(addr), "r"(bytes) : "memory")
#define MBAR_WAIT(addr, parity) do {                                           \
    asm volatile("{\n\t.reg .pred P;\n\t"                                      \
        "WL_%=:\n\t"                                                           \
        "mbarrier.try_wait.parity.acquire.cta.shared::cta.b64 P, [%0], %1, 0x989680;\n\t" \
        "@P bra WD_%=;\n\t"                                                    \
        "bra WL_%=;\n\t"                                                       \
        "WD_%=:\n\t}"                                                          \
        :: "r"(addr), "r"(parity) : "memory");                                 \
} while (0)

__device__ __forceinline__ void tma_load4d(uint32_t dst, const CUtensorMap* map,
                                           int x, int z, int tw, uint32_t mbar)
{
    asm volatile(
        "cp.async.bulk.tensor.4d.shared::cta.global.tile.mbarrier::complete_tx::bytes "
        "[%0], [%1, {%2, %3, %4, %5}], [%6];"
        :: "r"(dst), "l"(map), "r"(x), "r"(0), "r"(z), "r"(tw), "r"(mbar)
        : "memory");
}

// ---------------- main kernel: 2 CTAs/SM, PIX=8, R6 two-half structure ----
__global__ __launch_bounds__(NTHREADS, 2)
void tfma_occ2_kernel(const __grid_constant__ CUtensorMap tmapA,   // box {8,256,1,4}
                      const __grid_constant__ CUtensorMap tmapB,   // box {8,256,1,5}
                      const float* __restrict__ wptr,
                      const float* __restrict__ bptr,
                      const float* __restrict__ gptr,
                      float* __restrict__ out)
{
    extern __shared__ float sm[];
    float* part = sm + OFF_PART;
    float* scor = sm + OFF_SCOR;
    const uint32_t smem_base = (uint32_t)__cvta_generic_to_shared(sm);
    const uint32_t mb0 = smem_base + OFF_MBAR * 4;
    const uint32_t mb1 = mb0 + 8;
    const uint32_t dst0 = smem_base;                       // t = 0..3
    const uint32_t dst1 = smem_base + H0_BYTES;            // t = 4..8

    const int tid  = threadIdx.x;
    const int lane = tid & 31;
    const int wrp  = tid >> 5;
    const int p    = tid & (PIX - 1);   // 0..7
    const int cg   = tid >> 3;          // 0..63

    // static balanced tile range over 3136 8-px tiles: bid*392/37
    const int g0  = (int)(((long)blockIdx.x * 392) / 37);
    const int g1  = (int)(((long)(blockIdx.x + 1) * 392) / 37);
    const int cnt = g1 - g0;
    if (cnt <= 0) return;

    // preload weights to registers
    float wct[4], wot[4];
    #pragma unroll
    for (int ci = 0; ci < 4; ++ci) {
        wct[ci] = wptr[cg + (ci << 6)];
        wot[ci] = wptr[CC + cg + (ci << 6)];
    }
    const float bv    = bptr[0];
    const float gamma = gptr[0];

    if (tid == 0) {
        MBAR_INIT(mb0, 1);
        MBAR_INIT(mb1, 1);
    }
    __syncthreads();

    // prologue: both halves of tile g0
    {
        const int bidx = g0 / TILES_PER_B;
        const int pix0 = (g0 % TILES_PER_B) * PIX;
        if (tid == 0) {
            MBAR_EXPECT_TX(mb0, H0_BYTES);
            tma_load4d(dst0, &tmapA, pix0, bidx, 0, mb0);
            MBAR_EXPECT_TX(mb1, H1_BYTES);
            tma_load4d(dst1, &tmapB, pix0, bidx, H0_T, mb1);
        }
    }

    #pragma unroll 1
    for (int k = 0; k < cnt; ++k) {
        const int g    = g0 + k;
        const int bidx = g / TILES_PER_B;
        const int pix0 = (g % TILES_PER_B) * PIX;
        const int ph   = k & 1;

        const int gn    = g + 1;
        const int nbidx = gn / TILES_PER_B;
        const int npix0 = (gn % TILES_PER_B) * PIX;
        const bool more = (k + 1 < cnt);

        float rv[4][TT];
        float acc[TT];
        float accc = 0.f;
        #pragma unroll
        for (int t = 0; t < TT; ++t) acc[t] = 0.f;

        // ---- half 0: t = 0..3 ----
        MBAR_WAIT(mb0, ph);
        #pragma unroll
        for (int ci = 0; ci < 4; ++ci) {
            const int c = cg + (ci << 6);
            #pragma unroll
            for (int t = 0; t < H0_T; ++t) {
                rv[ci][t] = sm[(t * CC + c) * PIX + p];
                acc[t] = fmaf(rv[ci][t], wot[ci], acc[t]);
            }
        }
        __syncthreads();                       // half0 consumed by all
        if (more && tid == 0) {
            MBAR_EXPECT_TX(mb0, H0_BYTES);
            tma_load4d(dst0, &tmapA, npix0, nbidx, 0, mb0);
        }

        // ---- half 1: t = 4..8 ----
        MBAR_WAIT(mb1, ph);
        #pragma unroll
        for (int ci = 0; ci < 4; ++ci) {
            const int c = cg + (ci << 6);
            #pragma unroll
            for (int t = H0_T; t < TT; ++t) {
                rv[ci][t] = sm[(t * CC + c) * PIX + p];
                acc[t] = fmaf(rv[ci][t], wot[ci], acc[t]);
            }
            accc = fmaf(rv[ci][TT / 2], wct[ci], accc);
        }
        // warp partials: xor8 + xor16 combine the warp's four c-groups
        #pragma unroll
        for (int t = 0; t < TT; ++t) {
            acc[t] += __shfl_xor_sync(0xffffffffu, acc[t], 8);
            acc[t] += __shfl_xor_sync(0xffffffffu, acc[t], 16);
        }
        accc += __shfl_xor_sync(0xffffffffu, accc, 8);
        accc += __shfl_xor_sync(0xffffffffu, accc, 16);
        if (lane < PIX) {
            #pragma unroll
            for (int t = 0; t < TT; ++t)
                part[wrp * 80 + t * PIX + lane] = acc[t];
            part[wrp * 80 + TT * PIX + lane] = accc;
        }
        __syncthreads();                       // half1 consumed, partials visible
        if (more && tid == 0) {
            MBAR_EXPECT_TX(mb1, H1_BYTES);
            tma_load4d(dst1, &tmapB, npix0, nbidx, H0_T, mb1);
        }

        // ---- cross-warp reduce: 80 threads ----
        if (tid < 80) {
            float s = 0.f;
            #pragma unroll
            for (int w = 0; w < 16; ++w) s += part[w * 80 + tid];
            scor[tid] = s;
        }
        __syncthreads();

        // ---- softmax + attended sum + residual (from registers) ----
        {
            const float centv = scor[TT * PIX + p];
            float a[TT];
            float m = -1e30f;
            #pragma unroll
            for (int t = 0; t < TT; ++t) {
                a[t] = scor[t * PIX + p] + centv + bv;
                m = fmaxf(m, a[t]);
            }
            float sum = 0.f;
            #pragma unroll
            for (int t = 0; t < TT; ++t) {
                a[t] = __expf(a[t] - m);
                sum += a[t];
            }
            const float inv = 1.f / sum;
            #pragma unroll
            for (int t = 0; t < TT; ++t) a[t] *= inv;

            float* ob = out + (size_t)bidx * CC * HWHW + pix0 + p;
            #pragma unroll
            for (int ci = 0; ci < 4; ++ci) {
                const int c = cg + (ci << 6);
                float s = 0.f;
                #pragma unroll
                for (int t = 0; t < TT; ++t)
                    s = fmaf(a[t], rv[ci][t], s);
                ob[(size_t)c * HWHW] = rv[ci][TT / 2] + gamma * s;
            }
        }
        // no trailing barrier: next iter gates on mbar waits + barriers
        // (scor rewrite happens after next tile's partials barrier; part
        //  rewrite requires passing this tile's reduce barrier)
    }
}

// ---------------- fallback kernel (proven cp.async path) ----------------
#define FB_NT 7
#define FB_CHUNKS 56
#define FB_TILEF (TT*CC*PIX)
#define FB_OFF_WC   (2*FB_TILEF)
#define FB_OFF_WO   (FB_OFF_WC + CC)
#define FB_OFF_PART (FB_OFF_WO + CC)
#define FB_OFF_SCOR (FB_OFF_PART + 16*80)
#define FB_SMEM_BYTES ((FB_OFF_SCOR + 80) * 4)

__device__ __forceinline__ void fb_issue_tile(uint32_t smem_dst_bytes,
                                              const float* __restrict__ src, int tid)
{
    const int q = tid & 1;
    const int c = tid >> 1;
    const float* g = src + (size_t)c * HWHW + q * 4;
    uint32_t s = smem_dst_bytes + (uint32_t)((c * PIX + q * 4) * 4);
    #pragma unroll
    for (int t = 0; t < TT; ++t) {
        asm volatile("cp.async.cg.shared.global [%0], [%1], 16;\n"
                     :: "r"(s), "l"(g) : "memory");
        g += (size_t)BB * CC * HWHW;
        s += CC * PIX * 4;
    }
}

__global__ __launch_bounds__(512, 1)
void tfma_fb_kernel(const float* __restrict__ seq,
                    const float* __restrict__ wptr,
                    const float* __restrict__ bptr,
                    const float* __restrict__ gptr,
                    float* __restrict__ out)
{
    extern __shared__ float sm[];
    float* wc   = sm + FB_OFF_WC;
    float* wo   = sm + FB_OFF_WO;
    float* part = sm + FB_OFF_PART;
    float* scor = sm + FB_OFF_SCOR;
    const uint32_t smem_base = (uint32_t)__cvta_generic_to_shared(sm);

    const int tid  = threadIdx.x;
    const int lane = tid & 31;
    const int wrp  = tid >> 5;
    const int p    = tid & (PIX - 1);
    const int cg   = tid >> 3;
    const int bidx  = blockIdx.x / FB_CHUNKS;
    const int chunk = blockIdx.x % FB_CHUNKS;
    const float* tbase = seq + (size_t)bidx * CC * HWHW;

    if (tid < CC) { wc[tid] = wptr[tid]; wo[tid] = wptr[CC + tid]; }

    fb_issue_tile(smem_base, tbase + (size_t)(chunk * FB_NT) * PIX, tid);
    asm volatile("cp.async.commit_group;\n" ::: "memory");

    const float bv    = bptr[0];
    const float gamma = gptr[0];
    float* obase0 = out + (size_t)bidx * CC * HWHW;

    for (int k = 0; k < FB_NT; ++k) {
        if (k + 1 < FB_NT)
            fb_issue_tile(smem_base + ((k & 1) ? 0 : FB_TILEF) * 4,
                          tbase + (size_t)((chunk * FB_NT + k + 1) * PIX), tid);
        asm volatile("cp.async.commit_group;\n" ::: "memory");
        asm volatile("cp.async.wait_group 1;\n" ::: "memory");
        __syncthreads();

        const float* tile = sm + ((k & 1) ? FB_TILEF : 0);
        const int pix0 = (chunk * FB_NT + k) * PIX;

        float rv[4][TT];
        float acc[TT]; float accc = 0.f;
        #pragma unroll
        for (int t = 0; t < TT; ++t) acc[t] = 0.f;
        #pragma unroll
        for (int ci = 0; ci < 4; ++ci) {
            const int c = cg + (ci << 6);
            const float wotv = wo[c], wctv = wc[c];
            #pragma unroll
            for (int t = 0; t < TT; ++t) {
                rv[ci][t] = tile[(t * CC + c) * PIX + p];
                acc[t] = fmaf(rv[ci][t], wotv, acc[t]);
                if (t == TT / 2) accc = fmaf(rv[ci][t], wctv, accc);
            }
        }
        #pragma unroll
        for (int t = 0; t < TT; ++t) {
            acc[t] += __shfl_xor_sync(0xffffffffu, acc[t], 8);
            acc[t] += __shfl_xor_sync(0xffffffffu, acc[t], 16);
        }
        accc += __shfl_xor_sync(0xffffffffu, accc, 8);
        accc += __shfl_xor_sync(0xffffffffu, accc, 16);
        if (lane < PIX) {
            #pragma unroll
            for (int t = 0; t < TT; ++t) part[wrp * 80 + t * PIX + lane] = acc[t];
            part[wrp * 80 + TT * PIX + lane] = accc;
        }
        __syncthreads();
        if (tid < 80) {
            float s = 0.f;
            #pragma unroll
            for (int g = 0; g < 16; ++g) s += part[g * 80 + tid];
            scor[tid] = s;
        }
        __syncthreads();
        {
            const float centv = scor[TT * PIX + p];
            float a[TT]; float m = -1e30f;
            #pragma unroll
            for (int t = 0; t < TT; ++t) { a[t] = scor[t * PIX + p] + centv + bv; m = fmaxf(m, a[t]); }
            float sum = 0.f;
            #pragma unroll
            for (int t = 0; t < TT; ++t) { a[t] = __expf(a[t] - m); sum += a[t]; }
            const float inv = 1.f / sum;
            #pragma unroll
            for (int t = 0; t < TT; ++t) a[t] *= inv;

            float* ob = obase0 + pix0 + p;
            #pragma unroll
            for (int ci = 0; ci < 4; ++ci) {
                const int c = cg + (ci << 6);
                float s = 0.f;
                #pragma unroll
                for (int t = 0; t < TT; ++t) s = fmaf(a[t], rv[ci][t], s);
                ob[(size_t)c * HWHW] = rv[ci][TT / 2] + gamma * s;
            }
        }
        __syncthreads();
    }
}

// ---------------- host ----------------
typedef CUresult (*EncodeTiledFn)(CUtensorMap*, CUtensorMapDataType, cuuint32_t, void*,
                                  const cuuint64_t*, const cuuint64_t*,
                                  const cuuint32_t*, const cuuint32_t*,
                                  CUtensorMapInterleave, CUtensorMapSwizzle,
                                  CUtensorMapL2promotion, CUtensorMapFloatOOBfill);

extern "C" void kernel_launch(void* const* d_in, const int* in_sizes, int n_in,
                              void* d_out, int out_size)
{
    (void)in_sizes; (void)n_in; (void)out_size;
    const float* seq   = (const float*)d_in[0];
    const float* w     = (const float*)d_in[1];
    const float* bv    = (const float*)d_in[2];
    const float* gamma = (const float*)d_in[3];
    float* out = (float*)d_out;

    void* fn = nullptr;
    cudaDriverEntryPointQueryResult qr = cudaDriverEntryPointSymbolNotFound;
    cudaGetDriverEntryPointByVersion("cuTensorMapEncodeTiled", &fn, 12000,
                                     cudaEnableDefault, &qr);

    bool tma_ok = false;
    CUtensorMap tmapA, tmapB;
    if (fn && qr == cudaDriverEntryPointSuccess) {
        cuuint64_t dims[4]    = {HWHW, CC, BB, TT};
        cuuint64_t strides[3] = {(cuuint64_t)HWHW * 4,
                                 (cuuint64_t)CC * HWHW * 4,
                                 (cuuint64_t)BB * CC * HWHW * 4};
        cuuint32_t estr[4]    = {1, 1, 1, 1};
        cuuint32_t boxA[4]    = {PIX, CC, 1, H0_T};
        cuuint32_t boxB[4]    = {PIX, CC, 1, H1_T};
        CUresult rA = ((EncodeTiledFn)fn)(
            &tmapA, CU_TENSOR_MAP_DATA_TYPE_FLOAT32, 4, (void*)seq,
            dims, strides, boxA, estr,
            CU_TENSOR_MAP_INTERLEAVE_NONE, CU_TENSOR_MAP_SWIZZLE_NONE,
            CU_TENSOR_MAP_L2_PROMOTION_L2_128B, CU_TENSOR_MAP_FLOAT_OOB_FILL_NONE);
        CUresult rB = ((EncodeTiledFn)fn)(
            &tmapB, CU_TENSOR_MAP_DATA_TYPE_FLOAT32, 4, (void*)seq,
            dims, strides, boxB, estr,
            CU_TENSOR_MAP_INTERLEAVE_NONE, CU_TENSOR_MAP_SWIZZLE_NONE,
            CU_TENSOR_MAP_L2_PROMOTION_L2_128B, CU_TENSOR_MAP_FLOAT_OOB_FILL_NONE);
        tma_ok = (rA == CUDA_SUCCESS && rB == CUDA_SUCCESS);
    }

    if (tma_ok) {
        cudaFuncSetAttribute(tfma_occ2_kernel,
                             cudaFuncAttributeMaxDynamicSharedMemorySize, SMEM_BYTES);
        tfma_occ2_kernel<<<GRID, NTHREADS, SMEM_BYTES>>>(tmapA, tmapB, w, bv, gamma, out);
    } else {
        cudaFuncSetAttribute(tfma_fb_kernel,
                             cudaFuncAttributeMaxDynamicSharedMemorySize, FB_SMEM_BYTES);
        tfma_fb_kernel<<<448, 512, FB_SMEM_BYTES>>>(seq, w, bv, gamma, out);
    }
}

// round 13
// speedup vs baseline: 1.5935x; 1.5935x over previous
#include <cuda_runtime.h>
#include <cuda.h>
#include <cstdint>

// ---------------- constants ----------------
#define TT    9
#define BB    8
#define CC    256
#define HWHW  3136
#define PIX   16
#define NTHREADS 1024
#define TILES_PER_B 196          // 3136/16
#define GRID  148                // persistent, 1 CTA/SM

#define H0_T  4                  // t = 0..3 (double-buffered A)
#define H1_T  5                  // t = 4..8 (single-buffered B)
#define A_FLOATS (H0_T*CC*PIX)   // 16384 floats = 65536 B
#define B_FLOATS (H1_T*CC*PIX)   // 20480 floats = 81920 B
#define A_BYTES  (A_FLOATS*4)
#define B_BYTES  (B_FLOATS*4)

// SMEM layout (float offsets)
#define OFF_A0   0
#define OFF_A1   (A_FLOATS)                  // 16384
#define OFF_B    (2*A_FLOATS)                // 32768
#define OFF_PART (OFF_B + B_FLOATS)          // 53248  [32 warps][144]
#define OFF_SCOR (OFF_PART + 32*144)         // 57856  [144]
#define OFF_MBAR (OFF_SCOR + 144)            // 58000  (3 x u64; byte 232000, 8B aligned)
#define SMEM_FLOATS (OFF_MBAR + 6)
#define SMEM_BYTES  (SMEM_FLOATS * 4)        // 232024 B  (<= 232448 cap)

// ---------------- PTX helpers ----------------
#define MBAR_INIT(addr, cnt) \
    asm volatile("mbarrier.init.shared.b64 [%0], %1;" :: "r"(addr), "r"(cnt) : "memory")
#define MBAR_EXPECT_TX(addr, bytes) \
    asm volatile("mbarrier.arrive.expect_tx.shared.b64 _, [%0], %1;" :: "r"(addr), "r"(bytes) : "memory")
#define MBAR_WAIT(addr, parity) do {                                           \
    asm volatile("{\n\t.reg .pred P;\n\t"                                      \
        "WL_%=:\n\t"                                                           \
        "mbarrier.try_wait.parity.acquire.cta.shared::cta.b64 P, [%0], %1, 0x989680;\n\t" \
        "@P bra WD_%=;\n\t"                                                    \
        "bra WL_%=;\n\t"                                                       \
        "WD_%=:\n\t}"                                                          \
        :: "r"(addr), "r"(parity) : "memory");                                 \
} while (0)

__device__ __forceinline__ void tma_load4d(uint32_t dst, const CUtensorMap* map,
                                           int x, int z, int tw, uint32_t mbar)
{
    asm volatile(
        "cp.async.bulk.tensor.4d.shared::cta.global.tile.mbarrier::complete_tx::bytes "
        "[%0], [%1, {%2, %3, %4, %5}], [%6];"
        :: "r"(dst), "l"(map), "r"(x), "r"(0), "r"(z), "r"(tw), "r"(mbar)
        : "memory");
}

// ---------------- main kernel ----------------
__global__ __launch_bounds__(NTHREADS, 1)
void tfma_r11_kernel(const __grid_constant__ CUtensorMap tmapA,   // box {16,256,1,4}
                     const __grid_constant__ CUtensorMap tmapB,   // box {16,256,1,5}
                     const float* __restrict__ wptr,
                     const float* __restrict__ bptr,   // unused (softmax shift-invariant)
                     const float* __restrict__ gptr,
                     float* __restrict__ out)
{
    extern __shared__ float sm[];
    float* part = sm + OFF_PART;
    float* scor = sm + OFF_SCOR;
    const uint32_t smem_base = (uint32_t)__cvta_generic_to_shared(sm);
    const uint32_t mbA0 = smem_base + OFF_MBAR * 4;
    const uint32_t mbA1 = mbA0 + 8;
    const uint32_t mbB  = mbA0 + 16;
    const uint32_t dstA0 = smem_base;
    const uint32_t dstA1 = smem_base + A_BYTES;
    const uint32_t dstB  = smem_base + 2 * A_BYTES;

    const int tid  = threadIdx.x;
    const int lane = tid & 31;
    const int wrp  = tid >> 5;
    const int p    = tid & (PIX - 1);   // 0..15
    const int cg   = tid >> 4;          // 0..63

    // static balanced tile range over 1568 tiles
    const int g0  = (int)(((long)blockIdx.x * 392) / 37);
    const int g1  = (int)(((long)(blockIdx.x + 1) * 392) / 37);
    const int cnt = g1 - g0;
    if (cnt <= 0) return;

    // preload w_other to registers. NOTE: w_center + bias shift every t's
    // score equally -> softmax is invariant to them -> dropped entirely.
    float wot[4];
    #pragma unroll
    for (int ci = 0; ci < 4; ++ci)
        wot[ci] = wptr[CC + cg + (ci << 6)];
    const float gamma = gptr[0];
    (void)bptr;

    if (tid == 0) {
        MBAR_INIT(mbA0, 1);
        MBAR_INIT(mbA1, 1);
        MBAR_INIT(mbB, 1);
    }
    __syncthreads();

    // prologue, in consumption order: A(g0)->A0, B(g0)->B, A(g0+1)->A1
    if (tid == 0) {
        const int b0 = g0 / TILES_PER_B;
        const int x0 = (g0 % TILES_PER_B) * PIX;
        MBAR_EXPECT_TX(mbA0, A_BYTES);
        tma_load4d(dstA0, &tmapA, x0, b0, 0, mbA0);
        MBAR_EXPECT_TX(mbB, B_BYTES);
        tma_load4d(dstB, &tmapB, x0, b0, H0_T, mbB);
        if (cnt > 1) {
            const int g = g0 + 1;
            MBAR_EXPECT_TX(mbA1, A_BYTES);
            tma_load4d(dstA1, &tmapA, (g % TILES_PER_B) * PIX, g / TILES_PER_B, 0, mbA1);
        }
    }

    #pragma unroll 1
    for (int k = 0; k < cnt; ++k) {
        const int g    = g0 + k;
        const int bidx = g / TILES_PER_B;
        const int pix0 = (g % TILES_PER_B) * PIX;

        float rv[4][TT];
        float acc[TT];
        #pragma unroll
        for (int t = 0; t < TT; ++t) acc[t] = 0.f;

        // ---- A half: t = 0..3 (slot k&1, phase (k>>1)&1) — issued 2 iters ago
        MBAR_WAIT((k & 1) ? mbA1 : mbA0, (k >> 1) & 1);
        {
            const float* buf = sm + ((k & 1) ? OFF_A1 : OFF_A0);
            #pragma unroll
            for (int ci = 0; ci < 4; ++ci) {
                const int c = cg + (ci << 6);
                #pragma unroll
                for (int t = 0; t < H0_T; ++t) {
                    rv[ci][t] = buf[(t * CC + c) * PIX + p];
                    acc[t] = fmaf(rv[ci][t], wot[ci], acc[t]);
                }
            }
        }
        __syncthreads();                       // bar1: A slot consumed by all

        // ---- B half: t = 4..8 (phase k&1) ----
        MBAR_WAIT(mbB, k & 1);
        #pragma unroll
        for (int ci = 0; ci < 4; ++ci) {
            const int c = cg + (ci << 6);
            #pragma unroll
            for (int t = H0_T; t < TT; ++t) {
                rv[ci][t] = sm[OFF_B + ((t - H0_T) * CC + c) * PIX + p];
                acc[t] = fmaf(rv[ci][t], wot[ci], acc[t]);
            }
        }
        // warp partials: xor16 combines the warp's two c-groups (same p)
        #pragma unroll
        for (int t = 0; t < TT; ++t)
            acc[t] += __shfl_xor_sync(0xffffffffu, acc[t], 16);
        if (lane < PIX) {
            #pragma unroll
            for (int t = 0; t < TT; ++t)
                part[wrp * 144 + t * PIX + lane] = acc[t];
        }
        __syncthreads();                       // bar2: B consumed + partials visible

        // issue next tiles in consumption order: B(k+1), then A(k+2)
        if (tid == 0) {
            if (k + 1 < cnt) {
                const int gn = g + 1;
                MBAR_EXPECT_TX(mbB, B_BYTES);
                tma_load4d(dstB, &tmapB, (gn % TILES_PER_B) * PIX,
                           gn / TILES_PER_B, H0_T, mbB);
            }
            if (k + 2 < cnt) {
                const int gn = g + 2;
                const uint32_t mb  = (k & 1) ? mbA1 : mbA0;
                const uint32_t dst = (k & 1) ? dstA1 : dstA0;
                MBAR_EXPECT_TX(mb, A_BYTES);
                tma_load4d(dst, &tmapA, (gn % TILES_PER_B) * PIX,
                           gn / TILES_PER_B, 0, mb);
            }
        }

        // ---- cross-warp reduce: 144 threads ----
        if (tid < 144) {
            float s = 0.f;
            #pragma unroll
            for (int w = 0; w < 32; ++w) s += part[w * 144 + tid];
            scor[tid] = s;
        }
        __syncthreads();                       // bar3: scor visible

        // ---- softmax (shift-free) + attended sum + residual ----
        {
            float a[TT];
            float m = -1e30f;
            #pragma unroll
            for (int t = 0; t < TT; ++t) {
                a[t] = scor[t * PIX + p];
                m = fmaxf(m, a[t]);
            }
            float sum = 0.f;
            #pragma unroll
            for (int t = 0; t < TT; ++t) {
                a[t] = __expf(a[t] - m);
                sum += a[t];
            }
            const float inv = 1.f / sum;
            #pragma unroll
            for (int t = 0; t < TT; ++t) a[t] *= inv;

            float* ob = out + (size_t)bidx * CC * HWHW + pix0 + p;
            #pragma unroll
            for (int ci = 0; ci < 4; ++ci) {
                const int c = cg + (ci << 6);
                float s = 0.f;
                #pragma unroll
                for (int t = 0; t < TT; ++t)
                    s = fmaf(a[t], rv[ci][t], s);
                ob[(size_t)c * HWHW] = rv[ci][TT / 2] + gamma * s;
            }
        }
        // Reuse safety (no trailing barrier):
        //  - part(k+1) writes happen after bar1(k+1) > bar3(k) >= all reduce(k)
        //    reads of part.  scor(k+1) writes happen after bar2(k+1) >
        //    bar1(k+1), by which point every thread finished softmax(k)'s
        //    scor reads (they must arrive at bar1(k+1)).
        //  - A slot k+2 is TMA-written only after bar2(k) > bar1(k) = all
        //    A(k) reads done.  B(k+1) written after bar2(k) = all B(k) reads.
    }
}

// ---------------- fallback kernel (proven cp.async path) ----------------
#define FBPIX 8
#define FB_NT 7
#define FB_CHUNKS 56
#define FB_TILEF (TT*CC*FBPIX)
#define FB_OFF_WC   (2*FB_TILEF)
#define FB_OFF_WO   (FB_OFF_WC + CC)
#define FB_OFF_PART (FB_OFF_WO + CC)
#define FB_OFF_SCOR (FB_OFF_PART + 16*80)
#define FB_SMEM_BYTES ((FB_OFF_SCOR + 80) * 4)

__device__ __forceinline__ void fb_issue_tile(uint32_t smem_dst_bytes,
                                              const float* __restrict__ src, int tid)
{
    const int q = tid & 1;
    const int c = tid >> 1;
    const float* g = src + (size_t)c * HWHW + q * 4;
    uint32_t s = smem_dst_bytes + (uint32_t)((c * FBPIX + q * 4) * 4);
    #pragma unroll
    for (int t = 0; t < TT; ++t) {
        asm volatile("cp.async.cg.shared.global [%0], [%1], 16;\n"
                     :: "r"(s), "l"(g) : "memory");
        g += (size_t)BB * CC * HWHW;
        s += CC * FBPIX * 4;
    }
}

__global__ __launch_bounds__(512, 1)
void tfma_fb_kernel(const float* __restrict__ seq,
                    const float* __restrict__ wptr,
                    const float* __restrict__ bptr,
                    const float* __restrict__ gptr,
                    float* __restrict__ out)
{
    extern __shared__ float sm[];
    float* wc   = sm + FB_OFF_WC;
    float* wo   = sm + FB_OFF_WO;
    float* part = sm + FB_OFF_PART;
    float* scor = sm + FB_OFF_SCOR;
    const uint32_t smem_base = (uint32_t)__cvta_generic_to_shared(sm);

    const int tid  = threadIdx.x;
    const int lane = tid & 31;
    const int wrp  = tid >> 5;
    const int p    = tid & (FBPIX - 1);
    const int cg   = tid >> 3;
    const int bidx  = blockIdx.x / FB_CHUNKS;
    const int chunk = blockIdx.x % FB_CHUNKS;
    const float* tbase = seq + (size_t)bidx * CC * HWHW;

    if (tid < CC) { wc[tid] = wptr[tid]; wo[tid] = wptr[CC + tid]; }

    fb_issue_tile(smem_base, tbase + (size_t)(chunk * FB_NT) * FBPIX, tid);
    asm volatile("cp.async.commit_group;\n" ::: "memory");

    const float bv    = bptr[0];
    const float gamma = gptr[0];
    float* obase0 = out + (size_t)bidx * CC * HWHW;

    for (int k = 0; k < FB_NT; ++k) {
        if (k + 1 < FB_NT)
            fb_issue_tile(smem_base + ((k & 1) ? 0 : FB_TILEF) * 4,
                          tbase + (size_t)((chunk * FB_NT + k + 1) * FBPIX), tid);
        asm volatile("cp.async.commit_group;\n" ::: "memory");
        asm volatile("cp.async.wait_group 1;\n" ::: "memory");
        __syncthreads();

        const float* tile = sm + ((k & 1) ? FB_TILEF : 0);
        const int pix0 = (chunk * FB_NT + k) * FBPIX;

        float rv[4][TT];
        float acc[TT]; float accc = 0.f;
        #pragma unroll
        for (int t = 0; t < TT; ++t) acc[t] = 0.f;
        #pragma unroll
        for (int ci = 0; ci < 4; ++ci) {
            const int c = cg + (ci << 6);
            const float wotv = wo[c], wctv = wc[c];
            #pragma unroll
            for (int t = 0; t < TT; ++t) {
                rv[ci][t] = tile[(t * CC + c) * FBPIX + p];
                acc[t] = fmaf(rv[ci][t], wotv, acc[t]);
                if (t == TT / 2) accc = fmaf(rv[ci][t], wctv, accc);
            }
        }
        #pragma unroll
        for (int t = 0; t < TT; ++t) {
            acc[t] += __shfl_xor_sync(0xffffffffu, acc[t], 8);
            acc[t] += __shfl_xor_sync(0xffffffffu, acc[t], 16);
        }
        accc += __shfl_xor_sync(0xffffffffu, accc, 8);
        accc += __shfl_xor_sync(0xffffffffu, accc, 16);
        if (lane < FBPIX) {
            #pragma unroll
            for (int t = 0; t < TT; ++t) part[wrp * 80 + t * FBPIX + lane] = acc[t];
            part[wrp * 80 + TT * FBPIX + lane] = accc;
        }
        __syncthreads();
        if (tid < 80) {
            float s = 0.f;
            #pragma unroll
            for (int g = 0; g < 16; ++g) s += part[g * 80 + tid];
            scor[tid] = s;
        }
        __syncthreads();
        {
            const float centv = scor[TT * FBPIX + p];
            float a[TT]; float m = -1e30f;
            #pragma unroll
            for (int t = 0; t < TT; ++t) { a[t] = scor[t * FBPIX + p] + centv + bv; m = fmaxf(m, a[t]); }
            float sum = 0.f;
            #pragma unroll
            for (int t = 0; t < TT; ++t) { a[t] = __expf(a[t] - m); sum += a[t]; }
            const float inv = 1.f / sum;
            #pragma unroll
            for (int t = 0; t < TT; ++t) a[t] *= inv;

            float* ob = obase0 + pix0 + p;
            #pragma unroll
            for (int ci = 0; ci < 4; ++ci) {
                const int c = cg + (ci << 6);
                float s = 0.f;
                #pragma unroll
                for (int t = 0; t < TT; ++t) s = fmaf(a[t], rv[ci][t], s);
                ob[(size_t)c * HWHW] = rv[ci][TT / 2] + gamma * s;
            }
        }
        __syncthreads();
    }
}

// ---------------- host ----------------
typedef CUresult (*EncodeTiledFn)(CUtensorMap*, CUtensorMapDataType, cuuint32_t, void*,
                                  const cuuint64_t*, const cuuint64_t*,
                                  const cuuint32_t*, const cuuint32_t*,
                                  CUtensorMapInterleave, CUtensorMapSwizzle,
                                  CUtensorMapL2promotion, CUtensorMapFloatOOBfill);

extern "C" void kernel_launch(void* const* d_in, const int* in_sizes, int n_in,
                              void* d_out, int out_size)
{
    (void)in_sizes; (void)n_in; (void)out_size;
    const float* seq   = (const float*)d_in[0];
    const float* w     = (const float*)d_in[1];
    const float* bv    = (const float*)d_in[2];
    const float* gamma = (const float*)d_in[3];
    float* out = (float*)d_out;

    void* fn = nullptr;
    cudaDriverEntryPointQueryResult qr = cudaDriverEntryPointSymbolNotFound;
    cudaGetDriverEntryPointByVersion("cuTensorMapEncodeTiled", &fn, 12000,
                                     cudaEnableDefault, &qr);

    bool tma_ok = false;
    CUtensorMap tmapA, tmapB;
    if (fn && qr == cudaDriverEntryPointSuccess) {
        cuuint64_t dims[4]    = {HWHW, CC, BB, TT};
        cuuint64_t strides[3] = {(cuuint64_t)HWHW * 4,
                                 (cuuint64_t)CC * HWHW * 4,
                                 (cuuint64_t)BB * CC * HWHW * 4};
        cuuint32_t estr[4]    = {1, 1, 1, 1};
        cuuint32_t boxA[4]    = {PIX, CC, 1, H0_T};
        cuuint32_t boxB[4]    = {PIX, CC, 1, H1_T};
        CUresult rA = ((EncodeTiledFn)fn)(
            &tmapA, CU_TENSOR_MAP_DATA_TYPE_FLOAT32, 4, (void*)seq,
            dims, strides, boxA, estr,
            CU_TENSOR_MAP_INTERLEAVE_NONE, CU_TENSOR_MAP_SWIZZLE_NONE,
            CU_TENSOR_MAP_L2_PROMOTION_L2_128B, CU_TENSOR_MAP_FLOAT_OOB_FILL_NONE);
        CUresult rB = ((EncodeTiledFn)fn)(
            &tmapB, CU_TENSOR_MAP_DATA_TYPE_FLOAT32, 4, (void*)seq,
            dims, strides, boxB, estr,
            CU_TENSOR_MAP_INTERLEAVE_NONE, CU_TENSOR_MAP_SWIZZLE_NONE,
            CU_TENSOR_MAP_L2_PROMOTION_L2_128B, CU_TENSOR_MAP_FLOAT_OOB_FILL_NONE);
        tma_ok = (rA == CUDA_SUCCESS && rB == CUDA_SUCCESS);
    }

    if (tma_ok) {
        cudaFuncSetAttribute(tfma_r11_kernel,
                             cudaFuncAttributeMaxDynamicSharedMemorySize, SMEM_BYTES);
        tfma_r11_kernel<<<GRID, NTHREADS, SMEM_BYTES>>>(tmapA, tmapB, w, bv, gamma, out);
    } else {
        cudaFuncSetAttribute(tfma_fb_kernel,
                             cudaFuncAttributeMaxDynamicSharedMemorySize, FB_SMEM_BYTES);
        tfma_fb_kernel<<<448, 512, FB_SMEM_BYTES>>>(seq, w, bv, gamma, out);
    }
}

// round 14
// speedup vs baseline: 1.6795x; 1.0540x over previous
#include <cuda_runtime.h>
#include <cstdint>

// ---------------- constants ----------------
#define TT    9
#define BB    8
#define CC    256
#define HWHW  3136
#define PIX   16
#define NTHREADS 1024
#define TILES_PER_B 196          // 3136/16
#define GRID  148                // persistent, 1 CTA/SM

#define H0_T  4                  // t = 0..3  (A half)
#define H1_T  5                  // t = 4..8  (B half)
#define A_FLOATS (H0_T*CC*PIX)   // 16384 floats = 65536 B
#define B_FLOATS (H1_T*CC*PIX)   // 20480 floats = 81920 B

// SMEM layout (float offsets)
#define OFF_A    0
#define OFF_B    (A_FLOATS)                  // 16384
#define OFF_PART (A_FLOATS + B_FLOATS)       // 36864  [32 warps][144]
#define OFF_SCOR (OFF_PART + 32*144)         // 41472  [144]
#define SMEM_FLOATS (OFF_SCOR + 144)
#define SMEM_BYTES  (SMEM_FLOATS * 4)        // 166464 B

// Coalesced half loader: thread = (q = tid&3, rb = tid>>2); row (t0+j, rb)
// is 16 floats (64 B); this thread copies its 16 B quarter for nt t-slices.
// A warp covers 8 consecutive c-rows -> 8 half-lines per warp-op.
__device__ __forceinline__ void cp_half(uint32_t dst_bytes,
                                        const float* __restrict__ src, // seq + b*CC*HW + pix0
                                        int q, int rb, int t0, int nt)
{
    const float* g = src + (size_t)t0 * BB * CC * HWHW + (size_t)rb * HWHW + q * 4;
    uint32_t s = dst_bytes + (uint32_t)((rb * PIX + q * 4) * 4);
    #pragma unroll
    for (int j = 0; j < nt; ++j) {
        asm volatile("cp.async.cg.shared.global [%0], [%1], 16;\n"
                     :: "r"(s), "l"(g) : "memory");
        g += (size_t)BB * CC * HWHW;    // next t
        s += CC * PIX * 4;              // 16384 B per t-slab
    }
}

#define COMMIT() asm volatile("cp.async.commit_group;\n" ::: "memory")
#define WAITG(n) asm volatile("cp.async.wait_group %0;\n" :: "n"(n) : "memory")

// ---------------- main kernel ----------------
__global__ __launch_bounds__(NTHREADS, 1)
void tfma_cp_kernel(const float* __restrict__ seq,
                    const float* __restrict__ wptr,
                    const float* __restrict__ bptr,   // unused: softmax shift-invariant
                    const float* __restrict__ gptr,
                    float* __restrict__ out)
{
    extern __shared__ float sm[];
    float* part = sm + OFF_PART;
    float* scor = sm + OFF_SCOR;
    const uint32_t smem_base = (uint32_t)__cvta_generic_to_shared(sm);
    const uint32_t dstA = smem_base;
    const uint32_t dstB = smem_base + A_FLOATS * 4;

    const int tid  = threadIdx.x;
    const int lane = tid & 31;
    const int wrp  = tid >> 5;
    const int p    = tid & (PIX - 1);   // 0..15
    const int cg   = tid >> 4;          // 0..63
    const int q    = tid & 3;           // load quarter
    const int rb   = tid >> 2;          // load row (c) 0..255

    // static balanced tile range over 1568 tiles
    const int g0  = (int)(((long)blockIdx.x * 392) / 37);
    const int g1  = (int)(((long)(blockIdx.x + 1) * 392) / 37);
    const int cnt = g1 - g0;
    if (cnt <= 0) return;

    // w_other only: w_center + bias shift all t equally -> softmax-invariant.
    float wot[4];
    #pragma unroll
    for (int ci = 0; ci < 4; ++ci)
        wot[ci] = wptr[CC + cg + (ci << 6)];
    const float gamma = gptr[0];
    (void)bptr;

    // prologue: A(g0), B(g0)
    {
        const int bidx = g0 / TILES_PER_B;
        const float* src = seq + (size_t)bidx * CC * HWHW + (g0 % TILES_PER_B) * PIX;
        cp_half(dstA, src, q, rb, 0, H0_T);
        COMMIT();
        cp_half(dstB, src, q, rb, H0_T, H1_T);
        COMMIT();
    }

    #pragma unroll 1
    for (int k = 0; k < cnt; ++k) {
        const int g    = g0 + k;
        const int bidx = g / TILES_PER_B;
        const int pix0 = (g % TILES_PER_B) * PIX;

        const int gn      = g + 1;
        const float* nsrc = seq + (size_t)(gn / TILES_PER_B) * CC * HWHW
                                + (gn % TILES_PER_B) * PIX;
        const bool more = (k + 1 < cnt);

        float rv[4][TT];
        float acc[TT];
        #pragma unroll
        for (int t = 0; t < TT; ++t) acc[t] = 0.f;

        // ---- wait A(k): exactly one group (B(k)) may remain pending ----
        WAITG(1);
        __syncthreads();                       // bar0: A visible to all

        #pragma unroll
        for (int ci = 0; ci < 4; ++ci) {
            const int c = cg + (ci << 6);
            #pragma unroll
            for (int t = 0; t < H0_T; ++t) {
                rv[ci][t] = sm[(t * CC + c) * PIX + p];
                acc[t] = fmaf(rv[ci][t], wot[ci], acc[t]);
            }
        }

        // ---- wait B(k): last issued group ----
        WAITG(0);
        __syncthreads();                       // bar1: A consumed by all + B visible

        // refill A with tile k+1 (slot free; lands behind B consumption)
        if (more) cp_half(dstA, nsrc, q, rb, 0, H0_T);
        COMMIT();

        #pragma unroll
        for (int ci = 0; ci < 4; ++ci) {
            const int c = cg + (ci << 6);
            #pragma unroll
            for (int t = H0_T; t < TT; ++t) {
                rv[ci][t] = sm[OFF_B + ((t - H0_T) * CC + c) * PIX + p];
                acc[t] = fmaf(rv[ci][t], wot[ci], acc[t]);
            }
        }
        // warp partials: xor16 combines the warp's two c-groups (same p)
        #pragma unroll
        for (int t = 0; t < TT; ++t)
            acc[t] += __shfl_xor_sync(0xffffffffu, acc[t], 16);
        if (lane < PIX) {
            #pragma unroll
            for (int t = 0; t < TT; ++t)
                part[wrp * 144 + t * PIX + lane] = acc[t];
        }
        __syncthreads();                       // bar2: B consumed + partials visible

        // refill B with tile k+1
        if (more) cp_half(dstB, nsrc, q, rb, H0_T, H1_T);
        COMMIT();

        // ---- cross-warp reduce: 144 threads ----
        if (tid < 144) {
            float s = 0.f;
            #pragma unroll
            for (int w = 0; w < 32; ++w) s += part[w * 144 + tid];
            scor[tid] = s;
        }
        __syncthreads();                       // bar3: scor visible

        // ---- softmax (shift-free) + attended sum + residual ----
        {
            float a[TT];
            float m = -1e30f;
            #pragma unroll
            for (int t = 0; t < TT; ++t) {
                a[t] = scor[t * PIX + p];
                m = fmaxf(m, a[t]);
            }
            float sum = 0.f;
            #pragma unroll
            for (int t = 0; t < TT; ++t) {
                a[t] = __expf(a[t] - m);
                sum += a[t];
            }
            const float inv = 1.f / sum;
            #pragma unroll
            for (int t = 0; t < TT; ++t) a[t] *= inv;

            float* ob = out + (size_t)bidx * CC * HWHW + pix0 + p;
            #pragma unroll
            for (int ci = 0; ci < 4; ++ci) {
                const int c = cg + (ci << 6);
                float s = 0.f;
                #pragma unroll
                for (int t = 0; t < TT; ++t)
                    s = fmaf(a[t], rv[ci][t], s);
                ob[(size_t)c * HWHW] = rv[ci][TT / 2] + gamma * s;
            }
        }
        // Reuse safety (no trailing barrier):
        //  - part(k+1) written after bar1(k+1) > bar3(k) >= reduce(k) reads.
        //  - scor(k+1) written after bar2(k+1) > bar0(k+1) >= softmax(k) reads.
        //  - A(k+1) cp.async issued after bar1(k) = all A(k) reads done.
        //    B(k+1) issued after bar2(k) = all B(k) reads done.
        //  - group counting: every iteration commits exactly 2 groups (A then
        //    B, possibly empty), so WAITG(1)/WAITG(0) positions are exact.
    }
}

extern "C" void kernel_launch(void* const* d_in, const int* in_sizes, int n_in,
                              void* d_out, int out_size)
{
    (void)in_sizes; (void)n_in; (void)out_size;
    const float* seq   = (const float*)d_in[0];
    const float* w     = (const float*)d_in[1];
    const float* bv    = (const float*)d_in[2];
    const float* gamma = (const float*)d_in[3];
    float* out = (float*)d_out;

    cudaFuncSetAttribute(tfma_cp_kernel,
                         cudaFuncAttributeMaxDynamicSharedMemorySize, SMEM_BYTES);
    tfma_cp_kernel<<<GRID, NTHREADS, SMEM_BYTES>>>(seq, w, bv, gamma, out);
}